// round 8
// baseline (speedup 1.0000x reference)
#include <cuda_runtime.h>
#include <cstdint>

#define NKEYS 50000
#define DDIM  64
#define NA    8
#define NB    256
#define KNN   50
#define DELTA 0.001f

// GEMM tiling
#define BQ   64
#define BK   256
#define KTP  258   // padded row length for transposed K (floats)

// Selection
#define CAP    4096
#define CHUNK  2048

// Output offsets (float32 elements)
#define OFF_MAX   0
#define OFF_ACT   256
#define OFF_VALS  512
#define OFF_IDX   2560
#define OFF_SCORE 104960

// Scratch (module-load allocation, allowed)
__device__ float g_d2[(size_t)NA * NB * NKEYS];   // 409.6 MB
__device__ float g_ksq[NA * NKEYS];
__device__ float g_qsq[NB];

// ---------------------------------------------------------------------------
// Reference-replica reduction over 64 contiguous floats, modeling LLVM
// loop-vectorizer output on AArch64 NEON:
//   VF=4, IC=2 -> 8 partial accumulators: P[c][j] covers k = 8i + 4c + j
//   parts combined lane-wise: A[j] = P[0][j] + P[1][j]
//   horizontal via faddp pairs: s = (A0+A1) + (A2+A3)
// Squares fused as fma (ffp-contract on).
// ---------------------------------------------------------------------------
__device__ __forceinline__ float reduce64_sq(const float* __restrict__ x) {
    float p0x=0.f,p0y=0.f,p0z=0.f,p0w=0.f;
    float p1x=0.f,p1y=0.f,p1z=0.f,p1w=0.f;
    #pragma unroll
    for (int i = 0; i < 8; i++) {
        float4 a = *(const float4*)(x + 8 * i);
        float4 b = *(const float4*)(x + 8 * i + 4);
        p0x = __fmaf_rn(a.x, a.x, p0x);
        p0y = __fmaf_rn(a.y, a.y, p0y);
        p0z = __fmaf_rn(a.z, a.z, p0z);
        p0w = __fmaf_rn(a.w, a.w, p0w);
        p1x = __fmaf_rn(b.x, b.x, p1x);
        p1y = __fmaf_rn(b.y, b.y, p1y);
        p1z = __fmaf_rn(b.z, b.z, p1z);
        p1w = __fmaf_rn(b.w, b.w, p1w);
    }
    float a0 = __fadd_rn(p0x, p1x);
    float a1 = __fadd_rn(p0y, p1y);
    float a2 = __fadd_rn(p0z, p1z);
    float a3 = __fadd_rn(p0w, p1w);
    return __fadd_rn(__fadd_rn(a0, a1), __fadd_rn(a2, a3));
}

// Same model for sum((q - k)^2)
__device__ __forceinline__ float reduce64_diff_sq(const float* __restrict__ q,
                                                  const float* __restrict__ k) {
    float p0[4] = {0.f,0.f,0.f,0.f};
    float p1[4] = {0.f,0.f,0.f,0.f};
    #pragma unroll
    for (int i = 0; i < 8; i++) {
        #pragma unroll
        for (int j = 0; j < 4; j++) {
            float d0 = __fsub_rn(q[8*i + j],     k[8*i + j]);
            float d1 = __fsub_rn(q[8*i + 4 + j], k[8*i + 4 + j]);
            p0[j] = __fmaf_rn(d0, d0, p0[j]);
            p1[j] = __fmaf_rn(d1, d1, p1[j]);
        }
    }
    float a0 = __fadd_rn(p0[0], p1[0]);
    float a1 = __fadd_rn(p0[1], p1[1]);
    float a2 = __fadd_rn(p0[2], p1[2]);
    float a3 = __fadd_rn(p0[3], p1[3]);
    return __fadd_rn(__fadd_rn(a0, a1), __fadd_rn(a2, a3));
}

// ---------------------------------------------------------------------------
__global__ void ksq_kernel(const float* __restrict__ keys) {
    int kk = blockIdx.x * 256 + threadIdx.x;
    if (kk >= NA * NKEYS) return;
    g_ksq[kk] = reduce64_sq(keys + (size_t)kk * DDIM);
}

__global__ void qsq_kernel(const float* __restrict__ q) {
    int b = threadIdx.x;
    g_qsq[b] = reduce64_sq(q + (size_t)b * DDIM);
}

// ---------------------------------------------------------------------------
// Distance GEMM, reference-replica rounding:
//   dot[b,n] = sequential fp32 FMA chain over k=0..63 (single accumulator,
//              Eigen gebp order)
//   d2 = fsub(fadd(qsq, ksq), fmul(2, dot))   [2*dot is exact]
// f32x2 FMA pairs two ADJACENT n's per instruction; each 32-bit lane is an
// independent sequential chain, so bit-exactness is preserved at 2x rate.
// ---------------------------------------------------------------------------
__global__ void __launch_bounds__(256, 1)
gemm_kernel(const float* __restrict__ query, const float* __restrict__ keys) {
    extern __shared__ char smraw[];
    unsigned long long* Qp = (unsigned long long*)smraw;          // [BQ][DDIM] (q,q) pairs, 32KB
    float* Kt = (float*)(smraw + BQ * DDIM * 8);                  // [DDIM][KTP], 66KB

    int t = threadIdx.x;
    int nt = blockIdx.x, bt = blockIdx.y, a = blockIdx.z;
    int n0 = nt * BK;

    // stage Q packed (q,q)
    #pragma unroll
    for (int i = 0; i < 4; i++) {
        int f4 = t + 256 * i;               // 1024 float4s = 64q x 16
        int qi = f4 >> 4, dc = f4 & 15;
        float4 v = *(const float4*)(query + (size_t)(bt * BQ + qi) * DDIM + dc * 4);
        unsigned long long* dst = Qp + qi * DDIM + dc * 4;
        unsigned ux = __float_as_uint(v.x), uy = __float_as_uint(v.y);
        unsigned uz = __float_as_uint(v.z), uw = __float_as_uint(v.w);
        dst[0] = ((unsigned long long)ux << 32) | ux;
        dst[1] = ((unsigned long long)uy << 32) | uy;
        dst[2] = ((unsigned long long)uz << 32) | uz;
        dst[3] = ((unsigned long long)uw << 32) | uw;
    }
    // stage K transposed: Kt[d][n_local]
    const float* kb = keys + (size_t)a * NKEYS * DDIM;
    #pragma unroll
    for (int i = 0; i < 16; i++) {
        int f4 = t + 256 * i;               // 4096 float4s = 256n x 16
        int ki = f4 >> 4, dc = f4 & 15;
        int n = n0 + ki;
        float4 v = make_float4(0.f, 0.f, 0.f, 0.f);
        if (n < NKEYS) v = *(const float4*)(kb + (size_t)n * DDIM + dc * 4);
        Kt[(dc * 4 + 0) * KTP + ki] = v.x;
        Kt[(dc * 4 + 1) * KTP + ki] = v.y;
        Kt[(dc * 4 + 2) * KTP + ki] = v.z;
        Kt[(dc * 4 + 3) * KTP + ki] = v.w;
    }
    __syncthreads();

    int tx = t & 31, ty = t >> 5;
    // thread covers q rows ty*8..ty*8+7, n-pairs 2*(tx+32j), j=0..3
    unsigned long long acc[8][4];
    #pragma unroll
    for (int i = 0; i < 8; i++)
        #pragma unroll
        for (int j = 0; j < 4; j++) acc[i][j] = 0ull;

    const unsigned long long* qb = Qp + (ty * 8) * DDIM;

    #pragma unroll 4
    for (int k = 0; k < DDIM; k++) {
        unsigned long long k2[4];
        const float* kr = Kt + k * KTP;
        #pragma unroll
        for (int j = 0; j < 4; j++)
            k2[j] = *(const unsigned long long*)(kr + 2 * (tx + 32 * j));
        unsigned long long q2[8];
        #pragma unroll
        for (int i = 0; i < 8; i++)
            q2[i] = qb[i * DDIM + k];
        #pragma unroll
        for (int i = 0; i < 8; i++)
            #pragma unroll
            for (int j = 0; j < 4; j++)
                asm("fma.rn.f32x2 %0, %1, %2, %0;"
                    : "+l"(acc[i][j]) : "l"(q2[i]), "l"(k2[j]));
    }

    // epilogue
    #pragma unroll
    for (int j = 0; j < 4; j++) {
        int n = n0 + 2 * (tx + 32 * j);
        if (n >= NKEYS) continue;
        float2 ks2 = *(const float2*)(g_ksq + a * NKEYS + n);
        bool ok1 = (n + 1 < NKEYS);
        #pragma unroll
        for (int i = 0; i < 8; i++) {
            int b = bt * BQ + ty * 8 + i;
            float qs = g_qsq[b];
            unsigned long long v = acc[i][j];
            float lo = __uint_as_float((unsigned)(v & 0xffffffffull));
            float hi = __uint_as_float((unsigned)(v >> 32));
            float d0 = __fsub_rn(__fadd_rn(qs, ks2.x), __fmul_rn(2.0f, lo));
            float* orow = g_d2 + (size_t)(a * NB + b) * NKEYS;
            if (ok1) {
                float d1 = __fsub_rn(__fadd_rn(qs, ks2.y), __fmul_rn(2.0f, hi));
                float2 st = make_float2(d0, d1);
                *(float2*)(orow + n) = st;
            } else {
                orow[n] = d0;
            }
        }
    }
}

// ---------------------------------------------------------------------------
__device__ __forceinline__ float unpack_key(unsigned long long e) {
    unsigned int u = (unsigned)(e >> 32);
    u = (u & 0x80000000u) ? (u & 0x7fffffffu) : ~u;
    return __uint_as_float(u);
}

__device__ __forceinline__ void bitonic_sort(unsigned long long* buf, int t) {
    for (int k = 2; k <= CAP; k <<= 1) {
        for (int j = k >> 1; j > 0; j >>= 1) {
            #pragma unroll 1
            for (int i = t; i < CAP; i += 256) {
                int l = i ^ j;
                if (l > i) {
                    unsigned long long x = buf[i], y = buf[l];
                    bool up = ((i & k) == 0);
                    if ((x > y) == up) { buf[i] = y; buf[l] = x; }
                }
            }
            __syncthreads();
        }
    }
}

// ---------------------------------------------------------------------------
// Top-50 per (a,b) by (ref-replica d2, idx) — matches lax.top_k(-d2) order
// including lowest-index-first ties.
// ---------------------------------------------------------------------------
__global__ void __launch_bounds__(256)
select_kernel(const float* __restrict__ query, const float* __restrict__ keys,
              const float* __restrict__ vals, float* __restrict__ out) {
    __shared__ unsigned long long buf[CAP];
    __shared__ float qv[DDIM];
    __shared__ int   s_cnt;
    __shared__ float s_thr;
    __shared__ float s_w[KNN], s_wv[KNN];

    int t = threadIdx.x;
    int b = blockIdx.x, a = blockIdx.y;

    if (t < DDIM) qv[t] = query[b * DDIM + t];
    if (t == 0) { s_cnt = 0; s_thr = 3.4e38f; }
    __syncthreads();

    const float4* row = (const float4*)(g_d2 + (size_t)(a * NB + b) * NKEYS);
    const int NF4 = NKEYS / 4;  // 12500

    for (int base = 0; base < NKEYS; base += CHUNK) {
        float thr = s_thr;
        int f0 = base >> 2;
        #pragma unroll
        for (int j = 0; j < 2; j++) {
            int f4i = f0 + t + 256 * j;
            if (f4i < NF4) {
                float4 v = row[f4i];
                int n = f4i * 4;
                float vv[4] = {v.x, v.y, v.z, v.w};
                #pragma unroll
                for (int c = 0; c < 4; c++) {
                    if (vv[c] <= thr) {
                        int pos = atomicAdd(&s_cnt, 1);
                        unsigned int u = __float_as_uint(vv[c]);
                        u = (u & 0x80000000u) ? ~u : (u | 0x80000000u);
                        buf[pos] = ((unsigned long long)u << 32) | (unsigned)(n + c);
                    }
                }
            }
        }
        __syncthreads();
        if (s_cnt > CHUNK) {  // cnt <= CAP always (cnt <= 2048+50 at chunk start)
            int cnt = s_cnt;
            for (int i = cnt + t; i < CAP; i += 256) buf[i] = 0xFFFFFFFFFFFFFFFFull;
            __syncthreads();
            bitonic_sort(buf, t);
            if (t == 0) {
                s_cnt = KNN;
                s_thr = unpack_key(buf[KNN - 1]);
            }
            __syncthreads();
        }
    }
    // final sort
    {
        int cnt = s_cnt;
        for (int i = cnt + t; i < CAP; i += 256) buf[i] = 0xFFFFFFFFFFFFFFFFull;
        __syncthreads();
        bitonic_sort(buf, t);
    }

    // direct recompute with the reference-replica vectorized reduction
    if (t < KNN) {
        int idx = (int)(buf[t] & 0xffffffffull);
        const float* kp = keys + ((size_t)a * NKEYS + idx) * DDIM;
        float dist = reduce64_diff_sq(qv, kp);
        float w = 1.0f / (dist + DELTA);
        s_w[t]  = w;
        s_wv[t] = w * vals[(size_t)a * NKEYS + idx];
        out[OFF_IDX   + (b * NA + a) * KNN + t] = (float)idx;
        out[OFF_SCORE + (b * NA + a) * KNN + t] = dist;
    }
    __syncthreads();
    if (t == 0) {
        float sw = 0.f, swv = 0.f;
        for (int i = 0; i < KNN; i++) { sw += s_w[i]; swv += s_wv[i]; }
        out[OFF_VALS + b * NA + a] = swv / sw;
    }
}

// ---------------------------------------------------------------------------
__global__ void finalize_kernel(float* __restrict__ out) {
    int b = threadIdx.x;
    if (b < NB) {
        float best = out[OFF_VALS + b * NA];
        int arg = 0;
        #pragma unroll
        for (int a = 1; a < NA; a++) {
            float v = out[OFF_VALS + b * NA + a];
            if (v > best) { best = v; arg = a; }
        }
        out[OFF_MAX + b] = best;
        out[OFF_ACT + b] = (float)arg;
    }
}

// ---------------------------------------------------------------------------
extern "C" void kernel_launch(void* const* d_in, const int* in_sizes, int n_in,
                              void* d_out, int out_size) {
    const float* query = (const float*)d_in[0];
    const float* keys  = (const float*)d_in[1];
    const float* vals  = (const float*)d_in[2];
    float* out = (float*)d_out;

    const int gemm_smem = BQ * DDIM * 8 + DDIM * KTP * 4;  // 32768 + 66048 = 98816 B
    cudaFuncSetAttribute(gemm_kernel,
                         cudaFuncAttributeMaxDynamicSharedMemorySize, gemm_smem);

    ksq_kernel<<<(NA * NKEYS + 255) / 256, 256>>>(keys);
    qsq_kernel<<<1, 256>>>(query);

    dim3 gg((NKEYS + BK - 1) / BK, NB / BQ, NA);
    gemm_kernel<<<gg, 256, gemm_smem>>>(query, keys);

    dim3 gs(NB, NA);
    select_kernel<<<gs, 256>>>(query, keys, vals, out);

    finalize_kernel<<<1, 256>>>(out);
}

// round 9
// speedup vs baseline: 1.7769x; 1.7769x over previous
#include <cuda_runtime.h>
#include <cstdint>

#define NKEYS 50000
#define DDIM  64
#define NA    8
#define NB    256
#define KNN   50
#define DELTA 0.001f

// GEMM tiling
#define BQ   64
#define BK   256
#define KTP  258   // padded row length for transposed K (floats)

// Selection
#define SCHUNK 1024
#define STG    1088

// Output offsets (float32 elements)
#define OFF_MAX   0
#define OFF_ACT   256
#define OFF_VALS  512
#define OFF_IDX   2560
#define OFF_SCORE 104960

// Scratch (module-load allocation, allowed)
__device__ float g_d2[(size_t)NA * NB * NKEYS];   // 409.6 MB
__device__ float g_ksq[NA * NKEYS];
__device__ float g_qsq[NB];

// ---------------------------------------------------------------------------
// Reference-replica reduction (LLVM AArch64 NEON: VF=4, IC=2, faddp horiz).
// DO NOT TOUCH — bit-exactness verified in R8.
// ---------------------------------------------------------------------------
__device__ __forceinline__ float reduce64_sq(const float* __restrict__ x) {
    float p0x=0.f,p0y=0.f,p0z=0.f,p0w=0.f;
    float p1x=0.f,p1y=0.f,p1z=0.f,p1w=0.f;
    #pragma unroll
    for (int i = 0; i < 8; i++) {
        float4 a = *(const float4*)(x + 8 * i);
        float4 b = *(const float4*)(x + 8 * i + 4);
        p0x = __fmaf_rn(a.x, a.x, p0x);
        p0y = __fmaf_rn(a.y, a.y, p0y);
        p0z = __fmaf_rn(a.z, a.z, p0z);
        p0w = __fmaf_rn(a.w, a.w, p0w);
        p1x = __fmaf_rn(b.x, b.x, p1x);
        p1y = __fmaf_rn(b.y, b.y, p1y);
        p1z = __fmaf_rn(b.z, b.z, p1z);
        p1w = __fmaf_rn(b.w, b.w, p1w);
    }
    float a0 = __fadd_rn(p0x, p1x);
    float a1 = __fadd_rn(p0y, p1y);
    float a2 = __fadd_rn(p0z, p1z);
    float a3 = __fadd_rn(p0w, p1w);
    return __fadd_rn(__fadd_rn(a0, a1), __fadd_rn(a2, a3));
}

__device__ __forceinline__ float reduce64_diff_sq(const float* __restrict__ q,
                                                  const float* __restrict__ k) {
    float p0[4] = {0.f,0.f,0.f,0.f};
    float p1[4] = {0.f,0.f,0.f,0.f};
    #pragma unroll
    for (int i = 0; i < 8; i++) {
        #pragma unroll
        for (int j = 0; j < 4; j++) {
            float d0 = __fsub_rn(q[8*i + j],     k[8*i + j]);
            float d1 = __fsub_rn(q[8*i + 4 + j], k[8*i + 4 + j]);
            p0[j] = __fmaf_rn(d0, d0, p0[j]);
            p1[j] = __fmaf_rn(d1, d1, p1[j]);
        }
    }
    float a0 = __fadd_rn(p0[0], p1[0]);
    float a1 = __fadd_rn(p0[1], p1[1]);
    float a2 = __fadd_rn(p0[2], p1[2]);
    float a3 = __fadd_rn(p0[3], p1[3]);
    return __fadd_rn(__fadd_rn(a0, a1), __fadd_rn(a2, a3));
}

// ---------------------------------------------------------------------------
__global__ void ksq_kernel(const float* __restrict__ keys) {
    int kk = blockIdx.x * 256 + threadIdx.x;
    if (kk >= NA * NKEYS) return;
    g_ksq[kk] = reduce64_sq(keys + (size_t)kk * DDIM);
}

__global__ void qsq_kernel(const float* __restrict__ q) {
    int b = threadIdx.x;
    g_qsq[b] = reduce64_sq(q + (size_t)b * DDIM);
}

// ---------------------------------------------------------------------------
// Distance GEMM, reference-replica rounding (unchanged from R8).
// ---------------------------------------------------------------------------
__global__ void __launch_bounds__(256, 1)
gemm_kernel(const float* __restrict__ query, const float* __restrict__ keys) {
    extern __shared__ char smraw[];
    unsigned long long* Qp = (unsigned long long*)smraw;          // [BQ][DDIM] (q,q) pairs
    float* Kt = (float*)(smraw + BQ * DDIM * 8);                  // [DDIM][KTP]

    int t = threadIdx.x;
    int nt = blockIdx.x, bt = blockIdx.y, a = blockIdx.z;
    int n0 = nt * BK;

    #pragma unroll
    for (int i = 0; i < 4; i++) {
        int f4 = t + 256 * i;
        int qi = f4 >> 4, dc = f4 & 15;
        float4 v = *(const float4*)(query + (size_t)(bt * BQ + qi) * DDIM + dc * 4);
        unsigned long long* dst = Qp + qi * DDIM + dc * 4;
        unsigned ux = __float_as_uint(v.x), uy = __float_as_uint(v.y);
        unsigned uz = __float_as_uint(v.z), uw = __float_as_uint(v.w);
        dst[0] = ((unsigned long long)ux << 32) | ux;
        dst[1] = ((unsigned long long)uy << 32) | uy;
        dst[2] = ((unsigned long long)uz << 32) | uz;
        dst[3] = ((unsigned long long)uw << 32) | uw;
    }
    const float* kb = keys + (size_t)a * NKEYS * DDIM;
    #pragma unroll
    for (int i = 0; i < 16; i++) {
        int f4 = t + 256 * i;
        int ki = f4 >> 4, dc = f4 & 15;
        int n = n0 + ki;
        float4 v = make_float4(0.f, 0.f, 0.f, 0.f);
        if (n < NKEYS) v = *(const float4*)(kb + (size_t)n * DDIM + dc * 4);
        Kt[(dc * 4 + 0) * KTP + ki] = v.x;
        Kt[(dc * 4 + 1) * KTP + ki] = v.y;
        Kt[(dc * 4 + 2) * KTP + ki] = v.z;
        Kt[(dc * 4 + 3) * KTP + ki] = v.w;
    }
    __syncthreads();

    int tx = t & 31, ty = t >> 5;
    unsigned long long acc[8][4];
    #pragma unroll
    for (int i = 0; i < 8; i++)
        #pragma unroll
        for (int j = 0; j < 4; j++) acc[i][j] = 0ull;

    const unsigned long long* qb = Qp + (ty * 8) * DDIM;

    #pragma unroll 4
    for (int k = 0; k < DDIM; k++) {
        unsigned long long k2[4];
        const float* kr = Kt + k * KTP;
        #pragma unroll
        for (int j = 0; j < 4; j++)
            k2[j] = *(const unsigned long long*)(kr + 2 * (tx + 32 * j));
        unsigned long long q2[8];
        #pragma unroll
        for (int i = 0; i < 8; i++)
            q2[i] = qb[i * DDIM + k];
        #pragma unroll
        for (int i = 0; i < 8; i++)
            #pragma unroll
            for (int j = 0; j < 4; j++)
                asm("fma.rn.f32x2 %0, %1, %2, %0;"
                    : "+l"(acc[i][j]) : "l"(q2[i]), "l"(k2[j]));
    }

    #pragma unroll
    for (int j = 0; j < 4; j++) {
        int n = n0 + 2 * (tx + 32 * j);
        if (n >= NKEYS) continue;
        float2 ks2 = *(const float2*)(g_ksq + a * NKEYS + n);
        bool ok1 = (n + 1 < NKEYS);
        #pragma unroll
        for (int i = 0; i < 8; i++) {
            int b = bt * BQ + ty * 8 + i;
            float qs = g_qsq[b];
            unsigned long long v = acc[i][j];
            float lo = __uint_as_float((unsigned)(v & 0xffffffffull));
            float hi = __uint_as_float((unsigned)(v >> 32));
            float d0 = __fsub_rn(__fadd_rn(qs, ks2.x), __fmul_rn(2.0f, lo));
            float* orow = g_d2 + (size_t)(a * NB + b) * NKEYS;
            if (ok1) {
                float d1 = __fsub_rn(__fadd_rn(qs, ks2.y), __fmul_rn(2.0f, hi));
                __stcs((float2*)(orow + n), make_float2(d0, d1));
            } else {
                __stcs(orow + n, d0);
            }
        }
    }
}

// ---------------------------------------------------------------------------
__device__ __forceinline__ float unpack_key(unsigned long long e) {
    unsigned int u = (unsigned)(e >> 32);
    u = (u & 0x80000000u) ? (u & 0x7fffffffu) : ~u;
    return __uint_as_float(u);
}

// padding key: value +inf, max idx -> sorts after every real key, unpacks to +inf
#define PADKEY ((0xFF800000ull << 32) | 0xFFFFFFFFull)

// ---------------------------------------------------------------------------
// Top-50 per (a,b): incremental sorted top-64 with 64-wide bitonic merges.
// Exact (value, idx) ordering — identical result to the full sort.
// ---------------------------------------------------------------------------
__global__ void __launch_bounds__(256)
select_kernel(const float* __restrict__ query, const float* __restrict__ keys,
              const float* __restrict__ vals, float* __restrict__ out) {
    __shared__ unsigned long long s_top[64];
    __shared__ unsigned long long s_stg[STG];
    __shared__ unsigned long long s_mrg[64];
    __shared__ float s_mins[256];
    __shared__ int   s_cnt;
    __shared__ float s_thr;
    __shared__ float qv[DDIM];
    __shared__ float s_w[KNN], s_wv[KNN];

    int t = threadIdx.x;
    int b = blockIdx.x, a = blockIdx.y;

    if (t < DDIM) qv[t] = query[b * DDIM + t];
    if (t < 64)   s_top[t] = PADKEY;
    if (t == 0)   s_cnt = 0;

    const float4* row = (const float4*)(g_d2 + (size_t)(a * NB + b) * NKEYS);
    const int NF4 = NKEYS / 4;  // 12500

    // chunk-0 prefilter: 50th smallest of 256 per-thread mins (4 elems each).
    // Guarantees >=50 chunk-0 elements pass; expected ~55 pass.
    {
        float4 v = __ldcs(&row[t]);
        float m0 = fminf(fminf(v.x, v.y), fminf(v.z, v.w));
        s_mins[t] = m0;
        __syncthreads();
        for (int k = 2; k <= 256; k <<= 1) {
            for (int j = k >> 1; j > 0; j >>= 1) {
                int i = t, l = i ^ j;
                if (l > i) {
                    float x = s_mins[i], y = s_mins[l];
                    bool up = ((i & k) == 0);
                    if ((x > y) == up) { s_mins[i] = y; s_mins[l] = x; }
                }
                __syncthreads();
            }
        }
        if (t == 0) s_thr = s_mins[KNN - 1];
        __syncthreads();
    }

    for (int base = 0; base < NKEYS; base += SCHUNK) {
        float thr = s_thr;
        int f4i = (base >> 2) + t;
        if (f4i < NF4) {
            float4 v = __ldcs(&row[f4i]);
            int n = f4i * 4;
            float vv[4] = {v.x, v.y, v.z, v.w};
            #pragma unroll
            for (int c = 0; c < 4; c++) {
                if (vv[c] <= thr) {
                    int pos = atomicAdd(&s_cnt, 1);
                    unsigned int u = __float_as_uint(vv[c]);
                    u = (u & 0x80000000u) ? ~u : (u | 0x80000000u);
                    if (pos < STG)
                        s_stg[pos] = ((unsigned long long)u << 32) | (unsigned)(n + c);
                }
            }
        }
        __syncthreads();

        // drain staging in 64-wide merges
        for (;;) {
            int cnt = s_cnt;
            if (cnt <= 0) break;
            if (cnt > STG) cnt = STG;           // defensive (cannot trigger: <=1024/chunk)
            int m = cnt < 64 ? cnt : 64;
            if (t < 64) s_mrg[t] = (t < m) ? s_stg[cnt - m + t] : PADKEY;
            __syncthreads();
            // bitonic sort-64 ascending
            for (int k = 2; k <= 64; k <<= 1) {
                for (int j = k >> 1; j > 0; j >>= 1) {
                    if (t < 64) {
                        int i = t, l = i ^ j;
                        if (l > i) {
                            unsigned long long x = s_mrg[i], y = s_mrg[l];
                            bool up = ((i & k) == 0);
                            if ((x > y) == up) { s_mrg[i] = y; s_mrg[l] = x; }
                        }
                    }
                    __syncthreads();
                }
            }
            // keep lowest 64 of (top, mrg): reversed min-CE -> bitonic
            if (t < 64) {
                unsigned long long x = s_top[t], y = s_mrg[63 - t];
                s_top[t] = x < y ? x : y;
            }
            __syncthreads();
            // bitonic-merge cleanup -> ascending
            for (int j = 32; j > 0; j >>= 1) {
                if (t < 64) {
                    int i = t, l = i ^ j;
                    if (l > i) {
                        unsigned long long x = s_top[i], y = s_top[l];
                        if (x > y) { s_top[i] = y; s_top[l] = x; }
                    }
                }
                __syncthreads();
            }
            if (t == 0) {
                s_cnt = cnt - m;
                s_thr = unpack_key(s_top[KNN - 1]);
            }
            __syncthreads();
        }
    }

    // outputs: s_top[0..49] is the exact sorted top-50
    if (t < KNN) {
        int idx = (int)(s_top[t] & 0xffffffffull);
        const float* kp = keys + ((size_t)a * NKEYS + idx) * DDIM;
        float dist = reduce64_diff_sq(qv, kp);
        float w = 1.0f / (dist + DELTA);
        s_w[t]  = w;
        s_wv[t] = w * vals[(size_t)a * NKEYS + idx];
        out[OFF_IDX   + (b * NA + a) * KNN + t] = (float)idx;
        out[OFF_SCORE + (b * NA + a) * KNN + t] = dist;
    }
    __syncthreads();
    if (t == 0) {
        float sw = 0.f, swv = 0.f;
        for (int i = 0; i < KNN; i++) { sw += s_w[i]; swv += s_wv[i]; }
        out[OFF_VALS + b * NA + a] = swv / sw;
    }
}

// ---------------------------------------------------------------------------
__global__ void finalize_kernel(float* __restrict__ out) {
    int b = threadIdx.x;
    if (b < NB) {
        float best = out[OFF_VALS + b * NA];
        int arg = 0;
        #pragma unroll
        for (int a = 1; a < NA; a++) {
            float v = out[OFF_VALS + b * NA + a];
            if (v > best) { best = v; arg = a; }
        }
        out[OFF_MAX + b] = best;
        out[OFF_ACT + b] = (float)arg;
    }
}

// ---------------------------------------------------------------------------
extern "C" void kernel_launch(void* const* d_in, const int* in_sizes, int n_in,
                              void* d_out, int out_size) {
    const float* query = (const float*)d_in[0];
    const float* keys  = (const float*)d_in[1];
    const float* vals  = (const float*)d_in[2];
    float* out = (float*)d_out;

    const int gemm_smem = BQ * DDIM * 8 + DDIM * KTP * 4;  // 98816 B
    cudaFuncSetAttribute(gemm_kernel,
                         cudaFuncAttributeMaxDynamicSharedMemorySize, gemm_smem);

    ksq_kernel<<<(NA * NKEYS + 255) / 256, 256>>>(keys);
    qsq_kernel<<<1, 256>>>(query);

    dim3 gg((NKEYS + BK - 1) / BK, NB / BQ, NA);
    gemm_kernel<<<gg, 256, gemm_smem>>>(query, keys);

    dim3 gs(NB, NA);
    select_kernel<<<gs, 256>>>(query, keys, vals, out);

    finalize_kernel<<<1, 256>>>(out);
}